// round 9
// baseline (speedup 1.0000x reference)
#include <cuda_runtime.h>
#include <math.h>

// Fixed-shape problem: B=128, S=512, L=64
#define BB 128
#define SB 512
#define LL 64
#define GRID_MAIN 512         // blocks; each does 2 tiles of 64 pairs (1024 tiles)

__device__ float g_alpha_part[GRID_MAIN * LL];
__device__ float g_sc4[GRID_MAIN];     // per-(batch,quarter) score partial
__device__ int   g_cnt4[GRID_MAIN];    // per-(batch,quarter) mask count
__device__ int   g_count = 0;

// ---- packed f32x2 helpers (Blackwell FFMA2) ----
__device__ __forceinline__ unsigned long long pk2(float lo, float hi) {
    unsigned long long r;
    asm("mov.b64 %0, {%1,%2};" : "=l"(r) : "f"(lo), "f"(hi));
    return r;
}
__device__ __forceinline__ void fma2(unsigned long long &d, unsigned long long a, unsigned long long b) {
    asm("fma.rn.f32x2 %0, %1, %2, %0;" : "+l"(d) : "l"(a), "l"(b));
}
__device__ __forceinline__ float2 up2(unsigned long long v) {
    float2 r;
    asm("mov.b64 {%0,%1}, %2;" : "=f"(r.x), "=f"(r.y) : "l"(v));
    return r;
}

// ============================================================================
// Fused kernel.
//  Phase 1 (all 512 blocks): 2 tiles of the (64 pairs)x(64 i)x(64 k) exp-space
//    matvec, v_i = sum_j exp(T[i,j])*exp(emit[p,j]); accumulate w_p*log(v_i),
//    w_p = (b != 0) && mask[p]. T is stored in smem as DUPLICATED f32x2 pairs
//    so the inner loop is 4 LDS.64 + 1 LDS.128 + 8 FFMA2 (fma-pipe bound).
//  Phase 2 (all blocks): score partial for quarter q of batch b (g = 4b+q).
//  Phase 3 (last block via atomic counter): deterministic fp64 combine:
//    alpha = emit[0,0,:] + sum partials; logZ = LSE(alpha);
//    score_b = sum quarters + strans/etrans; out = (logZ - sum_b score_b)/B.
// ============================================================================
__global__ void __launch_bounds__(256, 4)
k_fused(const float* __restrict__ emit,
        const int*   __restrict__ labels,
        const int*   __restrict__ mask,
        const float* __restrict__ trans,
        const float* __restrict__ strans,
        const float* __restrict__ etrans,
        float* __restrict__ out) {
    __shared__ __align__(16) unsigned long long sTu[64 * 64];   // 32KB: (t,t) pairs, [k][i]
    __shared__ __align__(16) unsigned char scratch[16384];      // 16KB union

    float* sE   = (float*)scratch;          // [k][m] exp(emit), 64*64
    float* sRed = (float*)scratch;          // [i][ty] epilogue partials (overlays sE)

    const int tid = threadIdx.x;

    // ---- prologue: sTu[k*64+i] = pk2(exp(T[i][k])) ----
    {
        const int i  = tid & 63;
        const int kg = (tid >> 6) * 16;     // 16 consecutive k per thread
#pragma unroll
        for (int u = 0; u < 16; u++) {
            float v = __expf(trans[i * 64 + kg + u]);
            sTu[(kg + u) * 64 + i] = pk2(v, v);   // conflict-free STS.64 (stride 8B in i)
        }
    }

    const int tx = tid & 15;          // i-group: i = tx + 16u
    const int ty = tid >> 4;          // m-group: m = 4*ty..4*ty+3
    const int lm = tid >> 2;          // load: row m
    const int lk = (tid & 3) * 16;    // load: k-base

    float accA = 0.0f;                // meaningful for tid < 64

    for (int it = 0; it < 2; it++) {
        const int pbase = (blockIdx.x * 2 + it) * 64;

        // Load one emit row (16 contiguous floats), exp, transpose-store to sE.
        const float4* src = reinterpret_cast<const float4*>(emit + (pbase + lm) * LL + lk);
        float4 f0 = src[0], f1 = src[1], f2 = src[2], f3 = src[3];
        float ev[16] = {f0.x, f0.y, f0.z, f0.w, f1.x, f1.y, f1.z, f1.w,
                        f2.x, f2.y, f2.z, f2.w, f3.x, f3.y, f3.z, f3.w};

        const int p0 = pbase + 4 * ty;  // this thread's 4 pair rows
        float w0 = ((p0 + 0) >= SB && mask[p0 + 0] != 0) ? 1.0f : 0.0f;
        float w1 = ((p0 + 1) >= SB && mask[p0 + 1] != 0) ? 1.0f : 0.0f;
        float w2 = ((p0 + 2) >= SB && mask[p0 + 2] != 0) ? 1.0f : 0.0f;
        float w3 = ((p0 + 3) >= SB && mask[p0 + 3] != 0) ? 1.0f : 0.0f;

#pragma unroll
        for (int u = 0; u < 16; u++)
            sE[(lk + u) * 64 + lm] = __expf(ev[u]);
        __syncthreads();   // sE (and first-iter sTu) ready

        // 4 i-columns x 4 m-rows; acc packs m-pairs.
        unsigned long long a0x = 0, a0y = 0, a1x = 0, a1y = 0;
        unsigned long long a2x = 0, a2y = 0, a3x = 0, a3y = 0;
#pragma unroll 8
        for (int k = 0; k < 64; k++) {
            ulonglong2 ef = *reinterpret_cast<const ulonglong2*>(sE + k * 64 + 4 * ty);
            const unsigned long long* tr = sTu + k * 64 + tx;
            unsigned long long t0 = tr[0], t1 = tr[16], t2 = tr[32], t3 = tr[48];
            fma2(a0x, ef.x, t0); fma2(a0y, ef.y, t0);
            fma2(a1x, ef.x, t1); fma2(a1y, ef.y, t1);
            fma2(a2x, ef.x, t2); fma2(a2y, ef.y, t2);
            fma2(a3x, ef.x, t3); fma2(a3y, ef.y, t3);
        }

        // Epilogue: log, mask-weight, reduce over m.
        float2 lo, hi;
        lo = up2(a0x); hi = up2(a0y);
        float r0 = w0 * __logf(lo.x) + w1 * __logf(lo.y) + w2 * __logf(hi.x) + w3 * __logf(hi.y);
        lo = up2(a1x); hi = up2(a1y);
        float r1 = w0 * __logf(lo.x) + w1 * __logf(lo.y) + w2 * __logf(hi.x) + w3 * __logf(hi.y);
        lo = up2(a2x); hi = up2(a2y);
        float r2 = w0 * __logf(lo.x) + w1 * __logf(lo.y) + w2 * __logf(hi.x) + w3 * __logf(hi.y);
        lo = up2(a3x); hi = up2(a3y);
        float r3 = w0 * __logf(lo.x) + w1 * __logf(lo.y) + w2 * __logf(hi.x) + w3 * __logf(hi.y);

        __syncthreads();   // all sE reads done before sRed overlays it
        sRed[(tx +  0) * 17 + ty] = r0;
        sRed[(tx + 16) * 17 + ty] = r1;
        sRed[(tx + 32) * 17 + ty] = r2;
        sRed[(tx + 48) * 17 + ty] = r3;
        __syncthreads();

        if (tid < 64) {
            float s = 0.0f;
#pragma unroll
            for (int y2 = 0; y2 < 16; y2++) s += sRed[tid * 17 + y2];
            accA += s;
        }
        __syncthreads();   // sRed reads done before next sE fill / score reuse
    }

    if (tid < 64) g_alpha_part[blockIdx.x * LL + tid] = accA;

    // ---- Phase 2: score partial for (batch b, quarter q), g = blockIdx ----
    {
        const int g = blockIdx.x;
        const int b = g >> 2, q = g & 3;
        float acc = 0.0f; int cnt = 0;
        if (tid < 128) {
            const int s = q * 128 + tid;
            int lab = labels[b * SB + s];
            int mm  = mask[b * SB + s];
            if (mm != 0) {
                float v = emit[(b * SB + s) * LL + lab];
                if (s > 0) v += trans[labels[b * SB + s - 1] * LL + lab];
                acc = v; cnt = 1;
            }
        }
        float* rA = (float*)scratch;            // 512B
        int*   rC = (int*)(scratch + 512);      // 512B
        if (tid < 128) { rA[tid] = acc; rC[tid] = cnt; }
        __syncthreads();
#pragma unroll
        for (int o = 64; o > 0; o >>= 1) {
            if (tid < o) { rA[tid] += rA[tid + o]; rC[tid] += rC[tid + o]; }
            __syncthreads();
        }
        if (tid == 0) { g_sc4[g] = rA[0]; g_cnt4[g] = rC[0]; }
    }

    // ---- Phase 3: last block does the final combine ----
    // All global partials above precede the phase-2 __syncthreads; tid0
    // fences + counts — canonical threadFenceReduction pattern.
    __threadfence();
    volatile int* pLast = (volatile int*)(scratch + 16380);  // untouched by phase-2
    if (tid == 0) *pLast = (atomicAdd(&g_count, 1) == GRID_MAIN - 1) ? 1 : 0;
    __syncthreads();
    const int isLast = *pLast;
    __syncthreads();
    if (!isLast) return;
    __threadfence();

    double* sP  = (double*)scratch;            // 4*64 doubles  (2048B)
    double* sM  = (double*)(scratch + 2048);   // 64 doubles    (512B)
    double* sSc = (double*)(scratch + 2560);   // 128 doubles   (1024B)

    const int i  = tid & 63;
    const int q4 = tid >> 6;
    {
        double part = 0.0;
        const float* ap = g_alpha_part + q4 * 128 * LL + i;
#pragma unroll 8
        for (int j = 0; j < 128; j++) part += (double)ap[j * LL];
        sP[q4 * 64 + i] = part;
    }
    __syncthreads();

    double a = 0.0;
    if (tid < 64) {
        a = (double)emit[i] + ((sP[i] + sP[64 + i]) + (sP[128 + i] + sP[192 + i]));
        sM[i] = a;
    }
    __syncthreads();
#pragma unroll
    for (int o = 32; o > 0; o >>= 1) {
        if (tid < o) sM[tid] = fmax(sM[tid], sM[tid + o]);
        __syncthreads();
    }
    const double mx = sM[0];
    __syncthreads();
    if (tid < 64) sM[i] = exp(a - mx);
    __syncthreads();
#pragma unroll
    for (int o = 32; o > 0; o >>= 1) {
        if (tid < o) sM[tid] += sM[tid + o];
        __syncthreads();
    }
    const double sumE = sM[0];

    if (tid < 128) {
        const int b = tid;
        int cnt = g_cnt4[4 * b] + g_cnt4[4 * b + 1] + g_cnt4[4 * b + 2] + g_cnt4[4 * b + 3];
        double sc = (double)g_sc4[4 * b] + (double)g_sc4[4 * b + 1]
                  + (double)g_sc4[4 * b + 2] + (double)g_sc4[4 * b + 3];
        sc += (double)strans[labels[b * SB]] + (double)etrans[labels[b * SB + cnt - 1]];
        sSc[b] = sc;
    }
    __syncthreads();
#pragma unroll
    for (int o = 64; o > 0; o >>= 1) {
        if (tid < o) sSc[tid] += sSc[tid + o];
        __syncthreads();
    }

    if (tid == 0) {
        double logZ = mx + log(sumE);
        out[0] = (float)((logZ - sSc[0]) / (double)BB);
        g_count = 0;   // reset for next graph replay
    }
}

// ============================================================================
// kernel_launch — single fused kernel.
// Inputs: emit f32[B,S,L], labels i32[B,S], mask i32[B,S] (bool as int32),
//         transitions f32[L,L], strans f32[L], etrans f32[L]. Output f32[1].
// ============================================================================
extern "C" void kernel_launch(void* const* d_in, const int* in_sizes, int n_in,
                              void* d_out, int out_size) {
    const float* emit   = (const float*)d_in[0];
    const int*   labels = (const int*)d_in[1];
    const int*   mask   = (const int*)d_in[2];
    const float* trans  = (const float*)d_in[3];
    const float* strans = (const float*)d_in[4];
    const float* etrans = (const float*)d_in[5];
    float* out = (float*)d_out;

    k_fused<<<GRID_MAIN, 256>>>(emit, labels, mask, trans, strans, etrans, out);
}

// round 10
// speedup vs baseline: 1.2908x; 1.2908x over previous
#include <cuda_runtime.h>
#include <math.h>

// Fixed-shape problem: B=128, S=512, L=64
#define BB 128
#define SB 512
#define LL 64
#define LDE 68                // padded smem row stride (floats), 16B-aligned rows
#define GRID_MAIN 512         // blocks; each does 2 tiles of 64 pairs (1024 tiles)

__device__ float g_alpha_part[GRID_MAIN * LL];
__device__ float g_sc4[GRID_MAIN];     // per-(batch,quarter) score partial
__device__ int   g_cnt4[GRID_MAIN];    // per-(batch,quarter) mask count
__device__ int   g_count = 0;

// ---- packed f32x2 helpers (Blackwell FFMA2) ----
__device__ __forceinline__ unsigned long long pk2(float lo, float hi) {
    unsigned long long r;
    asm("mov.b64 %0, {%1,%2};" : "=l"(r) : "f"(lo), "f"(hi));
    return r;
}
__device__ __forceinline__ void fma2(unsigned long long &d, unsigned long long a, unsigned long long b) {
    asm("fma.rn.f32x2 %0, %1, %2, %0;" : "+l"(d) : "l"(a), "l"(b));
}
__device__ __forceinline__ float2 up2(unsigned long long v) {
    float2 r;
    asm("mov.b64 {%0,%1}, %2;" : "=f"(r.x), "=f"(r.y) : "l"(v));
    return r;
}

// ============================================================================
// Fused kernel. Phase 1 is the R3-measured GEMM structure (22.7us):
//   2 LDS.128 per k + register pk2 duplication — LDS-wavefront-light.
//   v_i = sum_j exp(T[i,j]) * exp(emit[p,j]); acc += w_p * log(v_i),
//   w_p = (b != 0) && mask[p].
// Phase 2: score partial for quarter q of batch b (g = 4b+q).
// Phase 3 (last block): deterministic fp64 combine -> out.
// ============================================================================
__global__ void __launch_bounds__(256, 4)
k_fused(const float* __restrict__ emit,
        const int*   __restrict__ labels,
        const int*   __restrict__ mask,
        const float* __restrict__ trans,
        const float* __restrict__ strans,
        const float* __restrict__ etrans,
        float* __restrict__ out) {
    __shared__ __align__(16) float sT[64 * LDE];   // sT[k*LDE + i] = exp(T[i][k])
    __shared__ __align__(16) float sE[64 * LDE];   // sE[k*LDE + m] = exp(emit[pair m][k])
    __shared__ __align__(16) float sRed[64 * 17];  // epilogue partials
    __shared__ int sLast;

    const int tid = threadIdx.x;

    // Load + exp + transpose T (once per block).
#pragma unroll
    for (int r = 0; r < 16; r++) {
        int idx = tid + 256 * r;                    // idx = i*64 + k
        sT[(idx & 63) * LDE + (idx >> 6)] = __expf(trans[idx]);
    }

    const int tx = tid & 15;          // output-column group (4 i's)
    const int ty = tid >> 4;          // pair-row group (4 m's)
    const int lm = tid >> 2;          // load: row m (0..63), 4 threads per row
    const int lk = (tid & 3) * 16;    // load: k-base

    float accA = 0.0f;                // meaningful for tid < 64

    for (int it = 0; it < 2; it++) {
        const int pbase = (blockIdx.x * 2 + it) * 64;

        // Load 16 contiguous floats of row (pbase+lm), k = lk..lk+15
        const float4* src = reinterpret_cast<const float4*>(emit + (pbase + lm) * LL + lk);
        float4 f0 = src[0], f1 = src[1], f2 = src[2], f3 = src[3];
        float ev[16] = {f0.x, f0.y, f0.z, f0.w, f1.x, f1.y, f1.z, f1.w,
                        f2.x, f2.y, f2.z, f2.w, f3.x, f3.y, f3.z, f3.w};

        const int p0 = pbase + 4 * ty;  // this thread's 4 pair rows (mask is int32)
        float w0 = ((p0 + 0) >= SB && mask[p0 + 0] != 0) ? 1.0f : 0.0f;
        float w1 = ((p0 + 1) >= SB && mask[p0 + 1] != 0) ? 1.0f : 0.0f;
        float w2 = ((p0 + 2) >= SB && mask[p0 + 2] != 0) ? 1.0f : 0.0f;
        float w3 = ((p0 + 3) >= SB && mask[p0 + 3] != 0) ? 1.0f : 0.0f;

#pragma unroll
        for (int u = 0; u < 16; u++)
            sE[(lk + u) * LDE + lm] = __expf(ev[u]);
        __syncthreads();   // sE (and first-iter sT) ready

        // 4x4 register tile: acc[mpair][i], packed m-pairs.
        unsigned long long a00 = 0ull, a01 = 0ull, a02 = 0ull, a03 = 0ull;
        unsigned long long a10 = 0ull, a11 = 0ull, a12 = 0ull, a13 = 0ull;
        const float* pT = sT + 4 * tx;
        const float* pE = sE + 4 * ty;
#pragma unroll 8
        for (int k = 0; k < 64; k++) {
            float4 tf = *reinterpret_cast<const float4*>(pT + k * LDE);
            ulonglong2 ef = *reinterpret_cast<const ulonglong2*>(pE + k * LDE);
            unsigned long long t0 = pk2(tf.x, tf.x);
            unsigned long long t1 = pk2(tf.y, tf.y);
            unsigned long long t2 = pk2(tf.z, tf.z);
            unsigned long long t3 = pk2(tf.w, tf.w);
            fma2(a00, ef.x, t0); fma2(a10, ef.y, t0);
            fma2(a01, ef.x, t1); fma2(a11, ef.y, t1);
            fma2(a02, ef.x, t2); fma2(a12, ef.y, t2);
            fma2(a03, ef.x, t3); fma2(a13, ef.y, t3);
        }

        // Epilogue: log, mask-weight, reduce over pairs.
        float2 u0, u1;
        u0 = up2(a00); u1 = up2(a10);
        float r0 = w0 * __logf(u0.x) + w1 * __logf(u0.y) + w2 * __logf(u1.x) + w3 * __logf(u1.y);
        u0 = up2(a01); u1 = up2(a11);
        float r1 = w0 * __logf(u0.x) + w1 * __logf(u0.y) + w2 * __logf(u1.x) + w3 * __logf(u1.y);
        u0 = up2(a02); u1 = up2(a12);
        float r2 = w0 * __logf(u0.x) + w1 * __logf(u0.y) + w2 * __logf(u1.x) + w3 * __logf(u1.y);
        u0 = up2(a03); u1 = up2(a13);
        float r3 = w0 * __logf(u0.x) + w1 * __logf(u0.y) + w2 * __logf(u1.x) + w3 * __logf(u1.y);

        sRed[(4 * tx + 0) * 17 + ty] = r0;
        sRed[(4 * tx + 1) * 17 + ty] = r1;
        sRed[(4 * tx + 2) * 17 + ty] = r2;
        sRed[(4 * tx + 3) * 17 + ty] = r3;
        __syncthreads();   // sRed ready; also all sE reads of this tile done

        if (tid < 64) {
            float s = 0.0f;
#pragma unroll
            for (int y2 = 0; y2 < 16; y2++) s += sRed[tid * 17 + y2];
            accA += s;
        }
        // Safe: next tile's sRed writes happen only after next sE-fill sync,
        // which the reducers must also reach.
    }

    if (tid < 64) g_alpha_part[blockIdx.x * LL + tid] = accA;
    __syncthreads();   // sRed reads done before phase-2 reuse

    // ---- Phase 2: score partial for (batch b, quarter q), g = blockIdx ----
    {
        const int g = blockIdx.x;
        const int b = g >> 2, q = g & 3;
        float acc = 0.0f; int cnt = 0;
        if (tid < 128) {
            const int s = q * 128 + tid;
            int lab = labels[b * SB + s];
            int mm  = mask[b * SB + s];
            if (mm != 0) {
                float v = emit[(b * SB + s) * LL + lab];
                if (s > 0) v += trans[labels[b * SB + s - 1] * LL + lab];
                acc = v; cnt = 1;
            }
        }
        float* rA = sRed;                       // 128 floats
        int*   rC = (int*)(sRed + 128);         // 128 ints
        if (tid < 128) { rA[tid] = acc; rC[tid] = cnt; }
        __syncthreads();
#pragma unroll
        for (int o = 64; o > 0; o >>= 1) {
            if (tid < o) { rA[tid] += rA[tid + o]; rC[tid] += rC[tid + o]; }
            __syncthreads();
        }
        if (tid == 0) { g_sc4[g] = rA[0]; g_cnt4[g] = rC[0]; }
    }

    // ---- Phase 3: last block does the final combine ----
    __threadfence();
    if (tid == 0) sLast = (atomicAdd(&g_count, 1) == GRID_MAIN - 1) ? 1 : 0;
    __syncthreads();
    if (!sLast) return;
    __threadfence();

    double* sP  = (double*)sE;                 // 4*64 doubles
    double* sM  = (double*)sE + 256;           // 64 doubles
    double* sSc = (double*)sE + 320;           // 128 doubles

    const int i  = tid & 63;
    const int q4 = tid >> 6;
    {
        double part = 0.0;
        const float* ap = g_alpha_part + q4 * 128 * LL + i;
#pragma unroll 8
        for (int j = 0; j < 128; j++) part += (double)ap[j * LL];
        sP[q4 * 64 + i] = part;
    }
    __syncthreads();

    double a = 0.0;
    if (tid < 64) {
        a = (double)emit[i] + ((sP[i] + sP[64 + i]) + (sP[128 + i] + sP[192 + i]));
        sM[i] = a;
    }
    __syncthreads();
#pragma unroll
    for (int o = 32; o > 0; o >>= 1) {
        if (tid < o) sM[tid] = fmax(sM[tid], sM[tid + o]);
        __syncthreads();
    }
    const double mx = sM[0];
    __syncthreads();
    if (tid < 64) sM[i] = exp(a - mx);
    __syncthreads();
#pragma unroll
    for (int o = 32; o > 0; o >>= 1) {
        if (tid < o) sM[tid] += sM[tid + o];
        __syncthreads();
    }
    const double sumE = sM[0];

    if (tid < 128) {
        const int b = tid;
        int cnt = g_cnt4[4 * b] + g_cnt4[4 * b + 1] + g_cnt4[4 * b + 2] + g_cnt4[4 * b + 3];
        double sc = (double)g_sc4[4 * b] + (double)g_sc4[4 * b + 1]
                  + (double)g_sc4[4 * b + 2] + (double)g_sc4[4 * b + 3];
        sc += (double)strans[labels[b * SB]] + (double)etrans[labels[b * SB + cnt - 1]];
        sSc[b] = sc;
    }
    __syncthreads();
#pragma unroll
    for (int o = 64; o > 0; o >>= 1) {
        if (tid < o) sSc[tid] += sSc[tid + o];
        __syncthreads();
    }

    if (tid == 0) {
        double logZ = mx + log(sumE);
        out[0] = (float)((logZ - sSc[0]) / (double)BB);
        g_count = 0;   // reset for next graph replay
    }
}

// ============================================================================
// kernel_launch — single fused kernel.
// Inputs: emit f32[B,S,L], labels i32[B,S], mask i32[B,S] (bool as int32),
//         transitions f32[L,L], strans f32[L], etrans f32[L]. Output f32[1].
// ============================================================================
extern "C" void kernel_launch(void* const* d_in, const int* in_sizes, int n_in,
                              void* d_out, int out_size) {
    const float* emit   = (const float*)d_in[0];
    const int*   labels = (const int*)d_in[1];
    const int*   mask   = (const int*)d_in[2];
    const float* trans  = (const float*)d_in[3];
    const float* strans = (const float*)d_in[4];
    const float* etrans = (const float*)d_in[5];
    float* out = (float*)d_out;

    k_fused<<<GRID_MAIN, 256>>>(emit, labels, mask, trans, strans, etrans, out);
}